// round 1
// baseline (speedup 1.0000x reference)
#include <cuda_runtime.h>
#include <cuda_bf16.h>

#define NN 50000
#define NE 800000
#define ET 850000   // NE + NN self loops
#define NS 0.2f

// ---------------- scratch (device globals; no allocation allowed) ------------
__device__ float g_h1[NN * 128];     // layer1 transformed features
__device__ float g_out1[NN * 128];   // layer1 aggregated output (+b1), relu applied at consumption
__device__ float g_as1[NN * 4];
__device__ float g_ad1[NN * 4];
__device__ float g_emax1[NN * 4];
__device__ float g_den1[NN * 4];
__device__ float g_h2[NN * 64];
__device__ float g_as2[NN];
__device__ float g_ad2[NN];
__device__ float g_emax2[NN];
__device__ float g_den2[NN];

__device__ __forceinline__ float lrelu(float v) { return v >= 0.f ? v : NS * v; }

__device__ __forceinline__ void atomicMaxF(float* addr, float v) {
    if (v >= 0.f) atomicMax((int*)addr, __float_as_int(v));
    else          atomicMin((unsigned int*)addr, __float_as_uint(v));
}

// ---------------- init: seed accumulators with biases, maxes with -inf -------
__global__ void k_init(const float* __restrict__ b1, const float* __restrict__ b2,
                       float* __restrict__ out) {
    int i = blockIdx.x * blockDim.x + threadIdx.x;
    const float ninf = __int_as_float(0xff800000);
    if (i < NN * 128) g_out1[i] = b1[i & 127];
    if (i < NN * 64)  out[i]    = b2[i & 63];
    if (i < NN * 4) { g_emax1[i] = ninf; g_den1[i] = 0.f; }
    if (i < NN)     { g_emax2[i] = ninf; g_den2[i] = 0.f; }
}

// ---------------- GEMM1: h1 = x @ W1   (128 -> 128) -------------------------
// block: 256 threads, tile 64 rows x 128 cols; thread: 8 rows x 4 cols
__global__ void k_gemm1(const float* __restrict__ X, const float* __restrict__ W) {
    __shared__ float sW[32 * 128];
    __shared__ float sX[32 * 65];    // transposed x tile [k][row], padded
    int t = threadIdx.x;
    int lane = t & 31, tr = t >> 5;
    int row0 = blockIdx.x * 64;

    float acc[8][4];
#pragma unroll
    for (int i = 0; i < 8; i++)
#pragma unroll
        for (int j = 0; j < 4; j++) acc[i][j] = 0.f;

    for (int kk = 0; kk < 128; kk += 32) {
        // load W chunk [32][128] = 1024 float4
        const float4* W4 = (const float4*)(W + kk * 128);
        float4* sW4 = (float4*)sW;
#pragma unroll
        for (int i = 0; i < 4; i++) sW4[t + 256 * i] = W4[t + 256 * i];
        // load X tile transposed: sX[k][r] = X[(row0+r)*128 + kk + k]
        int r = t >> 2, q = t & 3;
        int grow = row0 + r;
#pragma unroll
        for (int half = 0; half < 2; half++) {
            int q2 = q + 4 * half;
            float4 xv = make_float4(0.f, 0.f, 0.f, 0.f);
            if (grow < NN) xv = *(const float4*)(X + grow * 128 + kk + 4 * q2);
            sX[(4 * q2 + 0) * 65 + r] = xv.x;
            sX[(4 * q2 + 1) * 65 + r] = xv.y;
            sX[(4 * q2 + 2) * 65 + r] = xv.z;
            sX[(4 * q2 + 3) * 65 + r] = xv.w;
        }
        __syncthreads();
#pragma unroll
        for (int k = 0; k < 32; k++) {
            float4 wv = *(const float4*)(sW + k * 128 + 4 * lane);
#pragma unroll
            for (int i = 0; i < 8; i++) {
                float xr = sX[k * 65 + tr * 8 + i];
                acc[i][0] += xr * wv.x;
                acc[i][1] += xr * wv.y;
                acc[i][2] += xr * wv.z;
                acc[i][3] += xr * wv.w;
            }
        }
        __syncthreads();
    }
#pragma unroll
    for (int i = 0; i < 8; i++) {
        int row = row0 + tr * 8 + i;
        if (row < NN)
            *(float4*)(g_h1 + row * 128 + 4 * lane) =
                make_float4(acc[i][0], acc[i][1], acc[i][2], acc[i][3]);
    }
}

// ---------------- alpha1: per-node per-head attention coefficients -----------
// warp per node; lane handles 4 cols; head = lane>>3
__global__ void k_alpha1(const float* __restrict__ asr, const float* __restrict__ adt) {
    int n = blockIdx.x * 4 + (threadIdx.x >> 5);
    if (n >= NN) return;
    int lane = threadIdx.x & 31;
    float4 h = *(const float4*)(g_h1 + n * 128 + 4 * lane);
    float4 s = *(const float4*)(asr + 4 * lane);
    float4 d = *(const float4*)(adt + 4 * lane);
    float ps = h.x * s.x + h.y * s.y + h.z * s.z + h.w * s.w;
    float pd = h.x * d.x + h.y * d.y + h.z * d.z + h.w * d.w;
#pragma unroll
    for (int o = 4; o >= 1; o >>= 1) {
        ps += __shfl_down_sync(0xffffffffu, ps, o, 8);
        pd += __shfl_down_sync(0xffffffffu, pd, o, 8);
    }
    if ((lane & 7) == 0) {
        g_as1[n * 4 + (lane >> 3)] = ps;
        g_ad1[n * 4 + (lane >> 3)] = pd;
    }
}

// ---------------- edge pass helpers (layer 1, 4 heads) ----------------------
__device__ __forceinline__ void edge_sd(int e, const int* __restrict__ ei, int& s, int& d) {
    if (e < NE) { s = ei[e]; d = ei[NE + e]; }
    else        { s = e - NE; d = s; }
}

__global__ void k_max1(const int* __restrict__ ei) {
    int e = blockIdx.x * blockDim.x + threadIdx.x;
    if (e >= ET) return;
    int s, d; edge_sd(e, ei, s, d);
    float4 a = *(const float4*)(g_as1 + 4 * s);
    float4 b = *(const float4*)(g_ad1 + 4 * d);
    atomicMaxF(&g_emax1[4 * d + 0], lrelu(a.x + b.x));
    atomicMaxF(&g_emax1[4 * d + 1], lrelu(a.y + b.y));
    atomicMaxF(&g_emax1[4 * d + 2], lrelu(a.z + b.z));
    atomicMaxF(&g_emax1[4 * d + 3], lrelu(a.w + b.w));
}

__global__ void k_sum1(const int* __restrict__ ei) {
    int e = blockIdx.x * blockDim.x + threadIdx.x;
    if (e >= ET) return;
    int s, d; edge_sd(e, ei, s, d);
    float4 a = *(const float4*)(g_as1 + 4 * s);
    float4 b = *(const float4*)(g_ad1 + 4 * d);
    float4 m = *(const float4*)(g_emax1 + 4 * d);
    atomicAdd(&g_den1[4 * d + 0], __expf(lrelu(a.x + b.x) - m.x));
    atomicAdd(&g_den1[4 * d + 1], __expf(lrelu(a.y + b.y) - m.y));
    atomicAdd(&g_den1[4 * d + 2], __expf(lrelu(a.z + b.z) - m.z));
    atomicAdd(&g_den1[4 * d + 3], __expf(lrelu(a.w + b.w) - m.w));
}

// warp per edge; lane covers 4 consecutive cols
__global__ void k_scatter1(const int* __restrict__ ei) {
    int gid = blockIdx.x * blockDim.x + threadIdx.x;
    int w = gid >> 5, lane = gid & 31;
    if (w >= ET) return;
    int s, d; edge_sd(w, ei, s, d);
    float alpha = 0.f;
    if (lane < 4) {
        float ev = lrelu(g_as1[4 * s + lane] + g_ad1[4 * d + lane]);
        float ex = __expf(ev - g_emax1[4 * d + lane]);
        alpha = ex / (g_den1[4 * d + lane] + 1e-16f);
    }
    float a = __shfl_sync(0xffffffffu, alpha, lane >> 3);
    float4 h = *(const float4*)(g_h1 + s * 128 + 4 * lane);
    float* o = g_out1 + d * 128 + 4 * lane;
    atomicAdd(o + 0, h.x * a);
    atomicAdd(o + 1, h.y * a);
    atomicAdd(o + 2, h.z * a);
    atomicAdd(o + 3, h.w * a);
}

// ---------------- GEMM2: h2 = relu(out1) @ W2  (128 -> 64) ------------------
// block 256 threads, tile 64 rows x 64 cols; thread: 8 rows x 2 cols
__global__ void k_gemm2(const float* __restrict__ W) {
    __shared__ float sW[32 * 64];
    __shared__ float sX[32 * 65];
    int t = threadIdx.x;
    int lane = t & 31, tr = t >> 5;
    int row0 = blockIdx.x * 64;

    float acc[8][2];
#pragma unroll
    for (int i = 0; i < 8; i++) { acc[i][0] = 0.f; acc[i][1] = 0.f; }

    for (int kk = 0; kk < 128; kk += 32) {
        const float4* W4 = (const float4*)(W + kk * 64);
        float4* sW4 = (float4*)sW;
        sW4[t] = W4[t];
        sW4[t + 256] = W4[t + 256];
        int r = t >> 2, q = t & 3;
        int grow = row0 + r;
#pragma unroll
        for (int half = 0; half < 2; half++) {
            int q2 = q + 4 * half;
            float4 xv = make_float4(0.f, 0.f, 0.f, 0.f);
            if (grow < NN) xv = *(const float4*)(g_out1 + grow * 128 + kk + 4 * q2);
            sX[(4 * q2 + 0) * 65 + r] = fmaxf(xv.x, 0.f);
            sX[(4 * q2 + 1) * 65 + r] = fmaxf(xv.y, 0.f);
            sX[(4 * q2 + 2) * 65 + r] = fmaxf(xv.z, 0.f);
            sX[(4 * q2 + 3) * 65 + r] = fmaxf(xv.w, 0.f);
        }
        __syncthreads();
#pragma unroll
        for (int k = 0; k < 32; k++) {
            float2 wv = *(const float2*)(sW + k * 64 + 2 * lane);
#pragma unroll
            for (int i = 0; i < 8; i++) {
                float xr = sX[k * 65 + tr * 8 + i];
                acc[i][0] += xr * wv.x;
                acc[i][1] += xr * wv.y;
            }
        }
        __syncthreads();
    }
#pragma unroll
    for (int i = 0; i < 8; i++) {
        int row = row0 + tr * 8 + i;
        if (row < NN)
            *(float2*)(g_h2 + row * 64 + 2 * lane) = make_float2(acc[i][0], acc[i][1]);
    }
}

// ---------------- alpha2: per-node scalar coefficients ----------------------
__global__ void k_alpha2(const float* __restrict__ asr, const float* __restrict__ adt) {
    int n = blockIdx.x * 8 + (threadIdx.x >> 5);
    if (n >= NN) return;
    int lane = threadIdx.x & 31;
    float2 h = *(const float2*)(g_h2 + n * 64 + 2 * lane);
    float2 s = *(const float2*)(asr + 2 * lane);
    float2 d = *(const float2*)(adt + 2 * lane);
    float ps = h.x * s.x + h.y * s.y;
    float pd = h.x * d.x + h.y * d.y;
#pragma unroll
    for (int o = 16; o >= 1; o >>= 1) {
        ps += __shfl_xor_sync(0xffffffffu, ps, o);
        pd += __shfl_xor_sync(0xffffffffu, pd, o);
    }
    if (lane == 0) { g_as2[n] = ps; g_ad2[n] = pd; }
}

__global__ void k_max2(const int* __restrict__ ei) {
    int e = blockIdx.x * blockDim.x + threadIdx.x;
    if (e >= ET) return;
    int s, d; edge_sd(e, ei, s, d);
    atomicMaxF(&g_emax2[d], lrelu(g_as2[s] + g_ad2[d]));
}

__global__ void k_sum2(const int* __restrict__ ei) {
    int e = blockIdx.x * blockDim.x + threadIdx.x;
    if (e >= ET) return;
    int s, d; edge_sd(e, ei, s, d);
    float ev = lrelu(g_as2[s] + g_ad2[d]);
    atomicAdd(&g_den2[d], __expf(ev - g_emax2[d]));
}

// warp per edge; lane covers 2 cols
__global__ void k_scatter2(const int* __restrict__ ei, float* __restrict__ out) {
    int gid = blockIdx.x * blockDim.x + threadIdx.x;
    int w = gid >> 5, lane = gid & 31;
    if (w >= ET) return;
    int s, d; edge_sd(w, ei, s, d);
    float alpha = 0.f;
    if (lane == 0) {
        float ev = lrelu(g_as2[s] + g_ad2[d]);
        float ex = __expf(ev - g_emax2[d]);
        alpha = ex / (g_den2[d] + 1e-16f);
    }
    float a = __shfl_sync(0xffffffffu, alpha, 0);
    float2 h = *(const float2*)(g_h2 + s * 64 + 2 * lane);
    float* o = out + d * 64 + 2 * lane;
    atomicAdd(o + 0, h.x * a);
    atomicAdd(o + 1, h.y * a);
}

// ---------------- launch ------------------------------------------------------
extern "C" void kernel_launch(void* const* d_in, const int* in_sizes, int n_in,
                              void* d_out, int out_size) {
    const float* x   = (const float*)d_in[0];
    const int*   ei  = (const int*)d_in[1];
    const float* W1  = (const float*)d_in[2];
    const float* as1 = (const float*)d_in[3];
    const float* ad1 = (const float*)d_in[4];
    const float* b1  = (const float*)d_in[5];
    const float* W2  = (const float*)d_in[6];
    const float* as2 = (const float*)d_in[7];
    const float* ad2 = (const float*)d_in[8];
    const float* b2  = (const float*)d_in[9];
    float* out = (float*)d_out;

    k_init<<<(NN * 128 + 255) / 256, 256>>>(b1, b2, out);
    k_gemm1<<<(NN + 63) / 64, 256>>>(x, W1);
    k_alpha1<<<(NN + 3) / 4, 128>>>(as1, ad1);
    k_max1<<<(ET + 255) / 256, 256>>>(ei);
    k_sum1<<<(ET + 255) / 256, 256>>>(ei);
    {
        long long thr = (long long)ET * 32;
        k_scatter1<<<(unsigned)((thr + 255) / 256), 256>>>(ei);
    }
    k_gemm2<<<(NN + 63) / 64, 256>>>(W2);
    k_alpha2<<<(NN + 7) / 8, 256>>>(as2, ad2);
    k_max2<<<(ET + 255) / 256, 256>>>(ei);
    k_sum2<<<(ET + 255) / 256, 256>>>(ei);
    {
        long long thr = (long long)ET * 32;
        k_scatter2<<<(unsigned)((thr + 255) / 256), 256>>>(ei, out);
    }
}

// round 2
// speedup vs baseline: 2.1762x; 2.1762x over previous
#include <cuda_runtime.h>
#include <cuda_bf16.h>

#define NN 50000
#define NE 800000
#define ET 850000   // NE + NN self loops
#define NS 0.2f

// ---------------- scratch (device globals; no allocation allowed) ------------
__device__ float g_h1[NN * 128];     // layer1 transformed features
__device__ float g_out1[NN * 128];   // layer1 aggregated output (+b1)
__device__ float g_as1[NN * 4];
__device__ float g_ad1[NN * 4];
__device__ float g_h2[NN * 64];
__device__ float g_as2[NN];
__device__ float g_ad2[NN];
// CSR by destination
__device__ int g_deg[NN];
__device__ int g_off[NN + 1];
__device__ int g_cur[NN];
__device__ int g_srcidx[ET];

__device__ __forceinline__ float lrelu(float v) { return v >= 0.f ? v : NS * v; }

__device__ __forceinline__ void edge_sd(int e, const int* __restrict__ ei, int& s, int& d) {
    if (e < NE) { s = ei[e]; d = ei[NE + e]; }
    else        { s = e - NE; d = s; }
}

// ---------------- CSR construction ------------------------------------------
__global__ void k_deginit() {
    int i = blockIdx.x * blockDim.x + threadIdx.x;
    if (i < NN) g_deg[i] = 1;   // self loop
}

__global__ void k_hist(const int* __restrict__ ei) {
    int e = blockIdx.x * blockDim.x + threadIdx.x;
    if (e >= NE) return;
    atomicAdd(&g_deg[ei[NE + e]], 1);
}

// single block, 1024 threads, 4 elements/thread per chunk
__global__ void k_scan() {
    __shared__ int sh[1024];
    int carry = 0;
    for (int base = 0; base < NN; base += 4096) {
        int idx = base + threadIdx.x * 4;
        int v0 = (idx + 0 < NN) ? g_deg[idx + 0] : 0;
        int v1 = (idx + 1 < NN) ? g_deg[idx + 1] : 0;
        int v2 = (idx + 2 < NN) ? g_deg[idx + 2] : 0;
        int v3 = (idx + 3 < NN) ? g_deg[idx + 3] : 0;
        int ts = v0 + v1 + v2 + v3;
        sh[threadIdx.x] = ts;
        __syncthreads();
        for (int o = 1; o < 1024; o <<= 1) {
            int t = (threadIdx.x >= o) ? sh[threadIdx.x - o] : 0;
            __syncthreads();
            sh[threadIdx.x] += t;
            __syncthreads();
        }
        int excl = carry + sh[threadIdx.x] - ts;
        if (idx + 0 < NN) { g_off[idx + 0] = excl;            g_cur[idx + 0] = excl; }
        if (idx + 1 < NN) { g_off[idx + 1] = excl + v0;        g_cur[idx + 1] = excl + v0; }
        if (idx + 2 < NN) { g_off[idx + 2] = excl + v0 + v1;   g_cur[idx + 2] = excl + v0 + v1; }
        if (idx + 3 < NN) { g_off[idx + 3] = excl + v0 + v1 + v2; g_cur[idx + 3] = excl + v0 + v1 + v2; }
        carry += sh[1023];
        __syncthreads();
    }
    if (threadIdx.x == 0) g_off[NN] = carry;
}

__global__ void k_fill(const int* __restrict__ ei) {
    int e = blockIdx.x * blockDim.x + threadIdx.x;
    if (e >= ET) return;
    int s, d; edge_sd(e, ei, s, d);
    int pos = atomicAdd(&g_cur[d], 1);
    g_srcidx[pos] = s;
}

// ---------------- GEMM1: h1 = x @ W1   (128 -> 128) -------------------------
__global__ void k_gemm1(const float* __restrict__ X, const float* __restrict__ W) {
    __shared__ float sW[32 * 128];
    __shared__ float sX[32 * 65];
    int t = threadIdx.x;
    int lane = t & 31, tr = t >> 5;
    int row0 = blockIdx.x * 64;

    float acc[8][4];
#pragma unroll
    for (int i = 0; i < 8; i++)
#pragma unroll
        for (int j = 0; j < 4; j++) acc[i][j] = 0.f;

    for (int kk = 0; kk < 128; kk += 32) {
        const float4* W4 = (const float4*)(W + kk * 128);
        float4* sW4 = (float4*)sW;
#pragma unroll
        for (int i = 0; i < 4; i++) sW4[t + 256 * i] = W4[t + 256 * i];
        int r = t >> 2, q = t & 3;
        int grow = row0 + r;
#pragma unroll
        for (int half = 0; half < 2; half++) {
            int q2 = q + 4 * half;
            float4 xv = make_float4(0.f, 0.f, 0.f, 0.f);
            if (grow < NN) xv = *(const float4*)(X + grow * 128 + kk + 4 * q2);
            sX[(4 * q2 + 0) * 65 + r] = xv.x;
            sX[(4 * q2 + 1) * 65 + r] = xv.y;
            sX[(4 * q2 + 2) * 65 + r] = xv.z;
            sX[(4 * q2 + 3) * 65 + r] = xv.w;
        }
        __syncthreads();
#pragma unroll
        for (int k = 0; k < 32; k++) {
            float4 wv = *(const float4*)(sW + k * 128 + 4 * lane);
#pragma unroll
            for (int i = 0; i < 8; i++) {
                float xr = sX[k * 65 + tr * 8 + i];
                acc[i][0] += xr * wv.x;
                acc[i][1] += xr * wv.y;
                acc[i][2] += xr * wv.z;
                acc[i][3] += xr * wv.w;
            }
        }
        __syncthreads();
    }
#pragma unroll
    for (int i = 0; i < 8; i++) {
        int row = row0 + tr * 8 + i;
        if (row < NN)
            *(float4*)(g_h1 + row * 128 + 4 * lane) =
                make_float4(acc[i][0], acc[i][1], acc[i][2], acc[i][3]);
    }
}

// ---------------- alpha1 -----------------------------------------------------
__global__ void k_alpha1(const float* __restrict__ asr, const float* __restrict__ adt) {
    int n = blockIdx.x * 4 + (threadIdx.x >> 5);
    if (n >= NN) return;
    int lane = threadIdx.x & 31;
    float4 h = *(const float4*)(g_h1 + n * 128 + 4 * lane);
    float4 s = *(const float4*)(asr + 4 * lane);
    float4 d = *(const float4*)(adt + 4 * lane);
    float ps = h.x * s.x + h.y * s.y + h.z * s.z + h.w * s.w;
    float pd = h.x * d.x + h.y * d.y + h.z * d.z + h.w * d.w;
#pragma unroll
    for (int o = 4; o >= 1; o >>= 1) {
        ps += __shfl_down_sync(0xffffffffu, ps, o, 8);
        pd += __shfl_down_sync(0xffffffffu, pd, o, 8);
    }
    if ((lane & 7) == 0) {
        g_as1[n * 4 + (lane >> 3)] = ps;
        g_ad1[n * 4 + (lane >> 3)] = pd;
    }
}

// ---------------- gather1: fused online-softmax aggregation (4 heads) --------
// warp per dst node; lane handles cols [4*lane, 4*lane+4); head = lane>>3
__global__ void k_gather1(const float* __restrict__ b1) {
    int n = blockIdx.x * 8 + (threadIdx.x >> 5);
    if (n >= NN) return;
    int lane = threadIdx.x & 31, h = lane >> 3;
    float adh = g_ad1[4 * n + h];
    int beg = g_off[n], end = g_off[n + 1];

    float m = -__int_as_float(0x7f800000) * 0.f - 1e30f;  // large negative
    m = -3.4e38f;
    float den = 0.f;
    float4 acc = make_float4(0.f, 0.f, 0.f, 0.f);

    // software pipeline: prefetch src, coeff, row of next edge
    int s0 = 0; float a0 = 0.f; float4 hv0 = make_float4(0.f, 0.f, 0.f, 0.f);
    if (beg < end) {
        s0 = g_srcidx[beg];
        a0 = g_as1[4 * s0 + h];
        hv0 = *(const float4*)(g_h1 + (long)s0 * 128 + 4 * lane);
    }
    for (int j = beg; j < end; j++) {
        int s1 = 0; float a1 = 0.f; float4 hv1 = make_float4(0.f, 0.f, 0.f, 0.f);
        if (j + 1 < end) {
            s1 = g_srcidx[j + 1];
            a1 = g_as1[4 * s1 + h];
            hv1 = *(const float4*)(g_h1 + (long)s1 * 128 + 4 * lane);
        }
        float e = lrelu(a0 + adh);
        float nm = fmaxf(m, e);
        float sc = __expf(m - nm);
        float w = __expf(e - nm);
        den = den * sc + w;
        acc.x = acc.x * sc + w * hv0.x;
        acc.y = acc.y * sc + w * hv0.y;
        acc.z = acc.z * sc + w * hv0.z;
        acc.w = acc.w * sc + w * hv0.w;
        m = nm;
        s0 = s1; a0 = a1; hv0 = hv1;
    }
    float inv = 1.f / (den + 1e-16f);
    float4 bv = *(const float4*)(b1 + 4 * lane);
    *(float4*)(g_out1 + (long)n * 128 + 4 * lane) =
        make_float4(acc.x * inv + bv.x, acc.y * inv + bv.y,
                    acc.z * inv + bv.z, acc.w * inv + bv.w);
}

// ---------------- GEMM2: h2 = relu(out1) @ W2  (128 -> 64) ------------------
__global__ void k_gemm2(const float* __restrict__ W) {
    __shared__ float sW[32 * 64];
    __shared__ float sX[32 * 65];
    int t = threadIdx.x;
    int lane = t & 31, tr = t >> 5;
    int row0 = blockIdx.x * 64;

    float acc[8][2];
#pragma unroll
    for (int i = 0; i < 8; i++) { acc[i][0] = 0.f; acc[i][1] = 0.f; }

    for (int kk = 0; kk < 128; kk += 32) {
        const float4* W4 = (const float4*)(W + kk * 64);
        float4* sW4 = (float4*)sW;
        sW4[t] = W4[t];
        sW4[t + 256] = W4[t + 256];
        int r = t >> 2, q = t & 3;
        int grow = row0 + r;
#pragma unroll
        for (int half = 0; half < 2; half++) {
            int q2 = q + 4 * half;
            float4 xv = make_float4(0.f, 0.f, 0.f, 0.f);
            if (grow < NN) xv = *(const float4*)(g_out1 + grow * 128 + kk + 4 * q2);
            sX[(4 * q2 + 0) * 65 + r] = fmaxf(xv.x, 0.f);
            sX[(4 * q2 + 1) * 65 + r] = fmaxf(xv.y, 0.f);
            sX[(4 * q2 + 2) * 65 + r] = fmaxf(xv.z, 0.f);
            sX[(4 * q2 + 3) * 65 + r] = fmaxf(xv.w, 0.f);
        }
        __syncthreads();
#pragma unroll
        for (int k = 0; k < 32; k++) {
            float2 wv = *(const float2*)(sW + k * 64 + 2 * lane);
#pragma unroll
            for (int i = 0; i < 8; i++) {
                float xr = sX[k * 65 + tr * 8 + i];
                acc[i][0] += xr * wv.x;
                acc[i][1] += xr * wv.y;
            }
        }
        __syncthreads();
    }
#pragma unroll
    for (int i = 0; i < 8; i++) {
        int row = row0 + tr * 8 + i;
        if (row < NN)
            *(float2*)(g_h2 + row * 64 + 2 * lane) = make_float2(acc[i][0], acc[i][1]);
    }
}

// ---------------- alpha2 -----------------------------------------------------
__global__ void k_alpha2(const float* __restrict__ asr, const float* __restrict__ adt) {
    int n = blockIdx.x * 8 + (threadIdx.x >> 5);
    if (n >= NN) return;
    int lane = threadIdx.x & 31;
    float2 h = *(const float2*)(g_h2 + n * 64 + 2 * lane);
    float2 s = *(const float2*)(asr + 2 * lane);
    float2 d = *(const float2*)(adt + 2 * lane);
    float ps = h.x * s.x + h.y * s.y;
    float pd = h.x * d.x + h.y * d.y;
#pragma unroll
    for (int o = 16; o >= 1; o >>= 1) {
        ps += __shfl_xor_sync(0xffffffffu, ps, o);
        pd += __shfl_xor_sync(0xffffffffu, pd, o);
    }
    if (lane == 0) { g_as2[n] = ps; g_ad2[n] = pd; }
}

// ---------------- gather2: fused online-softmax aggregation (1 head) ---------
// warp per dst node; lane handles cols [2*lane, 2*lane+2)
__global__ void k_gather2(const float* __restrict__ b2, float* __restrict__ out) {
    int n = blockIdx.x * 8 + (threadIdx.x >> 5);
    if (n >= NN) return;
    int lane = threadIdx.x & 31;
    float adh = g_ad2[n];
    int beg = g_off[n], end = g_off[n + 1];

    float m = -3.4e38f;
    float den = 0.f;
    float2 acc = make_float2(0.f, 0.f);

    int s0 = 0; float a0 = 0.f; float2 hv0 = make_float2(0.f, 0.f);
    if (beg < end) {
        s0 = g_srcidx[beg];
        a0 = g_as2[s0];
        hv0 = *(const float2*)(g_h2 + (long)s0 * 64 + 2 * lane);
    }
    for (int j = beg; j < end; j++) {
        int s1 = 0; float a1 = 0.f; float2 hv1 = make_float2(0.f, 0.f);
        if (j + 1 < end) {
            s1 = g_srcidx[j + 1];
            a1 = g_as2[s1];
            hv1 = *(const float2*)(g_h2 + (long)s1 * 64 + 2 * lane);
        }
        float e = lrelu(a0 + adh);
        float nm = fmaxf(m, e);
        float sc = __expf(m - nm);
        float w = __expf(e - nm);
        den = den * sc + w;
        acc.x = acc.x * sc + w * hv0.x;
        acc.y = acc.y * sc + w * hv0.y;
        m = nm;
        s0 = s1; a0 = a1; hv0 = hv1;
    }
    float inv = 1.f / (den + 1e-16f);
    float2 bv = *(const float2*)(b2 + 2 * lane);
    *(float2*)(out + (long)n * 64 + 2 * lane) =
        make_float2(acc.x * inv + bv.x, acc.y * inv + bv.y);
}

// ---------------- launch ------------------------------------------------------
extern "C" void kernel_launch(void* const* d_in, const int* in_sizes, int n_in,
                              void* d_out, int out_size) {
    const float* x   = (const float*)d_in[0];
    const int*   ei  = (const int*)d_in[1];
    const float* W1  = (const float*)d_in[2];
    const float* as1 = (const float*)d_in[3];
    const float* ad1 = (const float*)d_in[4];
    const float* b1  = (const float*)d_in[5];
    const float* W2  = (const float*)d_in[6];
    const float* as2 = (const float*)d_in[7];
    const float* ad2 = (const float*)d_in[8];
    const float* b2  = (const float*)d_in[9];
    float* out = (float*)d_out;

    // CSR build (dst-bucketed)
    k_deginit<<<(NN + 255) / 256, 256>>>();
    k_hist<<<(NE + 255) / 256, 256>>>(ei);
    k_scan<<<1, 1024>>>();
    k_fill<<<(ET + 255) / 256, 256>>>(ei);

    // layer 1
    k_gemm1<<<(NN + 63) / 64, 256>>>(x, W1);
    k_alpha1<<<(NN + 3) / 4, 128>>>(as1, ad1);
    k_gather1<<<(NN + 7) / 8, 256>>>(b1);

    // layer 2
    k_gemm2<<<(NN + 63) / 64, 256>>>(W2);
    k_alpha2<<<(NN + 7) / 8, 256>>>(as2, ad2);
    k_gather2<<<(NN + 7) / 8, 256>>>(b2, out);
}